// round 1
// baseline (speedup 1.0000x reference)
#include <cuda_runtime.h>
#include <math.h>

#define BATCH   4
#define SEQ     2048
#define DIM     768
#define HEADS   12
#define HEAD_D  64
#define ATT_SCALE 0.125f   // 1/sqrt(64)

// ---------------- scratch (static device globals; no allocation) ----------------
__device__ float g_qkv[(size_t)BATCH * SEQ * 3 * DIM];   // [B,N,3C]  75.5 MB
__device__ float g_att[(size_t)BATCH * SEQ * DIM];       // [B,N,C]   25 MB

// =================================================================================
// GEMM-NT:  C[M,N] = A[M,K] * B[N,K]^T (+ bias)
// BM=128, BN=64, BK=16, 256 threads, 8x4 register tile per thread.
// =================================================================================
#define GBM 128
#define GBN 64
#define GBK 16

__global__ void __launch_bounds__(256)
gemm_nt_kernel(const float* __restrict__ A, const float* __restrict__ B,
               const float* __restrict__ bias, float* __restrict__ C,
               int M, int N, int K)
{
    __shared__ float As[GBK][GBM + 4];
    __shared__ float Bs[GBK][GBN + 4];

    const int tid = threadIdx.x;
    const int m0 = blockIdx.y * GBM;
    const int n0 = blockIdx.x * GBN;

    const int lr = tid >> 2;          // 0..63
    const int lk = (tid & 3) * 4;     // 0,4,8,12

    const int ty = tid >> 4;          // 0..15 -> rows ty*8..ty*8+7
    const int tx = tid & 15;          // 0..15 -> cols tx*4..tx*4+3

    float acc[8][4];
#pragma unroll
    for (int i = 0; i < 8; i++)
#pragma unroll
        for (int j = 0; j < 4; j++) acc[i][j] = 0.f;

    for (int k0 = 0; k0 < K; k0 += GBK) {
        // load A tile (128x16): rows lr and lr+64
        float4 a0 = *(const float4*)&A[(size_t)(m0 + lr) * K + k0 + lk];
        float4 a1 = *(const float4*)&A[(size_t)(m0 + lr + 64) * K + k0 + lk];
        // load B tile (64x16)
        float4 b0 = *(const float4*)&B[(size_t)(n0 + lr) * K + k0 + lk];

        As[lk + 0][lr] = a0.x; As[lk + 1][lr] = a0.y; As[lk + 2][lr] = a0.z; As[lk + 3][lr] = a0.w;
        As[lk + 0][lr + 64] = a1.x; As[lk + 1][lr + 64] = a1.y; As[lk + 2][lr + 64] = a1.z; As[lk + 3][lr + 64] = a1.w;
        Bs[lk + 0][lr] = b0.x; Bs[lk + 1][lr] = b0.y; Bs[lk + 2][lr] = b0.z; Bs[lk + 3][lr] = b0.w;
        __syncthreads();

#pragma unroll
        for (int kk = 0; kk < GBK; kk++) {
            float4 av0 = *(const float4*)&As[kk][ty * 8];
            float4 av1 = *(const float4*)&As[kk][ty * 8 + 4];
            float4 bv  = *(const float4*)&Bs[kk][tx * 4];
            float a[8] = {av0.x, av0.y, av0.z, av0.w, av1.x, av1.y, av1.z, av1.w};
            float b[4] = {bv.x, bv.y, bv.z, bv.w};
#pragma unroll
            for (int i = 0; i < 8; i++)
#pragma unroll
                for (int j = 0; j < 4; j++) acc[i][j] += a[i] * b[j];
        }
        __syncthreads();
    }

    float4 bb = make_float4(0.f, 0.f, 0.f, 0.f);
    if (bias) bb = *(const float4*)&bias[n0 + tx * 4];
#pragma unroll
    for (int i = 0; i < 8; i++) {
        float4 v = make_float4(acc[i][0] + bb.x, acc[i][1] + bb.y,
                               acc[i][2] + bb.z, acc[i][3] + bb.w);
        *(float4*)&C[(size_t)(m0 + ty * 8 + i) * N + n0 + tx * 4] = v;
    }
}

// =================================================================================
// Fused attention: per (b, h, 16 query rows) CTA.
//   S[16][2048] in shared -> double softmax in place -> O = P @ V
// 512 threads. K and V are streamed from global (each element read once per CTA,
// mostly L2 hits).
// =================================================================================
#define AT_ROWS 16
#define SPITCH  2052           // 2048 + 4 (16B-aligned, bank-stagger)
#define QPITCH  68
#define VPITCH  68
#define ATT_SMEM_FLOATS (AT_ROWS * SPITCH + AT_ROWS * QPITCH + 128 * VPITCH)
#define ATT_SMEM_BYTES  (ATT_SMEM_FLOATS * 4)

__global__ void __launch_bounds__(512)
attn_kernel(const float* __restrict__ qkv, float* __restrict__ att)
{
    extern __shared__ float sm[];
    float* S  = sm;                               // [16][SPITCH]
    float* Q  = sm + AT_ROWS * SPITCH;            // [16][QPITCH]
    float* Vt = Q + AT_ROWS * QPITCH;             // [128][VPITCH]

    const int b  = blockIdx.z;
    const int h  = blockIdx.y;
    const int n0 = blockIdx.x * AT_ROWS;
    const int tid = threadIdx.x;

    const size_t base = (size_t)b * SEQ * (3 * DIM) + (size_t)h * HEAD_D;
    const float* Qg = qkv + base;                 // + n*2304 + d
    const float* Kg = qkv + base + DIM;           // which = 1
    const float* Vg = qkv + base + 2 * DIM;       // which = 2

    // ---- load Q tile [16][64] ----
    if (tid < 256) {
        int r = tid >> 4;                 // 0..15
        int d = (tid & 15) * 4;           // 0..60
        float4 q4 = *(const float4*)&Qg[(size_t)(n0 + r) * (3 * DIM) + d];
        *(float4*)&Q[r * QPITCH + d] = q4;
    }
    __syncthreads();

    // ---- S = Q K^T * scale ----
    {
        const int r = tid & 7;                // rows r and r+8
        const int c = (tid >> 3) * 4;         // 0..252
        for (int m0 = 0; m0 < SEQ; m0 += 256) {
            float acc0[4] = {0.f, 0.f, 0.f, 0.f};
            float acc1[4] = {0.f, 0.f, 0.f, 0.f};
#pragma unroll 8
            for (int d4 = 0; d4 < HEAD_D; d4 += 4) {
                float4 q0 = *(const float4*)&Q[r * QPITCH + d4];
                float4 q1 = *(const float4*)&Q[(r + 8) * QPITCH + d4];
#pragma unroll
                for (int i = 0; i < 4; i++) {
                    float4 kv = *(const float4*)&Kg[(size_t)(m0 + c + i) * (3 * DIM) + d4];
                    acc0[i] += q0.x * kv.x + q0.y * kv.y + q0.z * kv.z + q0.w * kv.w;
                    acc1[i] += q1.x * kv.x + q1.y * kv.y + q1.z * kv.z + q1.w * kv.w;
                }
            }
#pragma unroll
            for (int i = 0; i < 4; i++) {
                S[r * SPITCH + m0 + c + i]       = acc0[i] * ATT_SCALE;
                S[(r + 8) * SPITCH + m0 + c + i] = acc1[i] * ATT_SCALE;
            }
        }
    }
    __syncthreads();

    // ---- double softmax, one warp per row ----
    const int warp = tid >> 5;
    const int lane = tid & 31;
    {
        float* row = S + warp * SPITCH;
        float mx = -1e30f;
        for (int j = lane; j < SEQ; j += 32) mx = fmaxf(mx, row[j]);
#pragma unroll
        for (int off = 16; off; off >>= 1) mx = fmaxf(mx, __shfl_xor_sync(~0u, mx, off));

        float sum = 0.f;
        for (int j = lane; j < SEQ; j += 32) {
            float e = __expf(row[j] - mx);
            row[j] = e;
            sum += e;
        }
#pragma unroll
        for (int off = 16; off; off >>= 1) sum += __shfl_xor_sync(~0u, sum, off);
        float inv = 1.0f / sum;       // NOTE: max(p) over the row == 1/sum exactly

        // second softmax: t = exp(p - max p) = exp(e*inv - inv)
        float z2 = 0.f;
        for (int j = lane; j < SEQ; j += 32) {
            float t = __expf(row[j] * inv - inv);
            row[j] = t;
            z2 += t;
        }
#pragma unroll
        for (int off = 16; off; off >>= 1) z2 += __shfl_xor_sync(~0u, z2, off);
        float inv2 = 1.0f / z2;
        for (int j = lane; j < SEQ; j += 32) row[j] *= inv2;
    }
    // no cross-warp S dependency for AV (warp w reads only its own row),
    // but Vt staging syncs everyone anyway.

    // ---- O = P @ V : warp handles its row; lane covers d = lane, lane+32 ----
    {
        float o0 = 0.f, o1 = 0.f;
        const float* prow = S + warp * SPITCH;
        for (int mb = 0; mb < SEQ; mb += 128) {
            __syncthreads();   // protect Vt from previous iter readers
            {
                int mm = tid >> 4;              // 0..31
                int d4 = (tid & 15) * 4;
#pragma unroll
                for (int jj = 0; jj < 4; jj++) {
                    int m = mm + jj * 32;
                    float4 v4 = *(const float4*)&Vg[(size_t)(mb + m) * (3 * DIM) + d4];
                    *(float4*)&Vt[m * VPITCH + d4] = v4;
                }
            }
            __syncthreads();
#pragma unroll 4
            for (int m = 0; m < 128; m += 4) {
                float4 p4 = *(const float4*)&prow[mb + m];
                float p[4] = {p4.x, p4.y, p4.z, p4.w};
#pragma unroll
                for (int u = 0; u < 4; u++) {
                    float va = Vt[(m + u) * VPITCH + lane];
                    float vb = Vt[(m + u) * VPITCH + lane + 32];
                    o0 += p[u] * va;
                    o1 += p[u] * vb;
                }
            }
        }
        float* Og = att + ((size_t)(b * SEQ + n0 + warp)) * DIM + h * HEAD_D;
        Og[lane]      = o0;
        Og[lane + 32] = o1;
    }
}

// =================================================================================
// launch
// =================================================================================
extern "C" void kernel_launch(void* const* d_in, const int* in_sizes, int n_in,
                              void* d_out, int out_size)
{
    const float* x      = (const float*)d_in[0];   // [4,2048,768]
    const float* w_qkv  = (const float*)d_in[1];   // [2304,768]
    const float* w_proj = (const float*)d_in[2];   // [768,768]
    const float* b_proj = (const float*)d_in[3];   // [768]
    float* out = (float*)d_out;                    // [4,2048,768]

    void* p0; cudaGetSymbolAddress(&p0, g_qkv);
    void* p1; cudaGetSymbolAddress(&p1, g_att);
    float* qkv = (float*)p0;
    float* att = (float*)p1;

    cudaFuncSetAttribute(attn_kernel, cudaFuncAttributeMaxDynamicSharedMemorySize,
                         ATT_SMEM_BYTES);

    const int M = BATCH * SEQ;   // 8192

    // 1) qkv = x @ w_qkv^T          C[8192, 2304]
    {
        dim3 grid((3 * DIM) / GBN, M / GBM);
        gemm_nt_kernel<<<grid, 256>>>(x, w_qkv, nullptr, qkv, M, 3 * DIM, DIM);
    }

    // 2) fused attention (QK^T, double softmax, PV)
    {
        dim3 grid(SEQ / AT_ROWS, HEADS, BATCH);
        attn_kernel<<<grid, 512, ATT_SMEM_BYTES>>>(qkv, att);
    }

    // 3) out = att @ w_proj^T + b   C[8192, 768]
    {
        dim3 grid(DIM / GBN, M / GBM);
        gemm_nt_kernel<<<grid, 256>>>(att, w_proj, b_proj, out, M, DIM, DIM);
    }
}